// round 15
// baseline (speedup 1.0000x reference)
#include <cuda_runtime.h>
#include <cuda_fp16.h>
#include <cstdint>

namespace {
constexpr int B_  = 4;
constexpr int C_  = 64;
constexpr int IC_ = 16;
constexpr int D_  = 8;
constexpr int H_  = 128;
constexpr int W_  = 128;
constexpr int MID_ = 4;
constexpr int HP_ = 64;
constexpr int L_  = 4096;
constexpr int F_  = 144;    // IC*3*3 = 9 * 16
constexpr int FV_ = 152;    // V rows padded: row 144 = ones, 145..151 = 0
constexpr float SCALE_ = 10.0f;
constexpr float LOG2E_ = 1.4426950408889634f;

// flash smem layout (bytes), k16-tiled swizzled operands
constexpr int TILE_B  = 4096;                 // 128 rows x 32B (Q/K/P)
constexpr int VTILE_B = 4864;                 // 152 rows x 32B (V)
constexpr int QK_PLANE = 9 * TILE_B;          // 36864
constexpr int V_PLANE  = 8 * VTILE_B;         // 38912
constexpr int Q_OFF = 0;                      // 36864
constexpr int K_OFF = 36864;                  // 2 bufs -> 110592
constexpr int V_OFF = 110592;                 // 2 bufs -> 188416
constexpr int P_OFF = 188416;                 // 32768 -> 221184
constexpr int ST_OFF = 221184;                // alphas 512
constexpr int FLASH_SMEM = ST_OFF + 512;      // 221696
}

// ============================================================
// helpers
// ============================================================
__device__ __forceinline__ void mma16816(float* c, const uint32_t* a,
                                         uint32_t b0, uint32_t b1) {
    asm volatile(
        "mma.sync.aligned.m16n8k16.row.col.f32.f16.f16.f32 "
        "{%0,%1,%2,%3}, {%4,%5,%6,%7}, {%8,%9}, {%0,%1,%2,%3};"
        : "+f"(c[0]), "+f"(c[1]), "+f"(c[2]), "+f"(c[3])
        : "r"(a[0]), "r"(a[1]), "r"(a[2]), "r"(a[3]), "r"(b0), "r"(b1));
}

__device__ __forceinline__ void ldsm_x4(uint32_t* r, uint32_t smaddr) {
    asm volatile("ldmatrix.sync.aligned.m8n8.x4.shared.b16 {%0,%1,%2,%3}, [%4];"
                 : "=r"(r[0]), "=r"(r[1]), "=r"(r[2]), "=r"(r[3]) : "r"(smaddr));
}
__device__ __forceinline__ void ldsm_x2(uint32_t* r, uint32_t smaddr) {
    asm volatile("ldmatrix.sync.aligned.m8n8.x2.shared.b16 {%0,%1}, [%2];"
                 : "=r"(r[0]), "=r"(r[1]) : "r"(smaddr));
}

__device__ __forceinline__ void cp_async16(uint32_t smaddr, const void* gptr) {
    asm volatile("cp.async.cg.shared.global [%0], [%1], 16;"
                 :: "r"(smaddr), "l"(gptr) : "memory");
}
#define CP_COMMIT() asm volatile("cp.async.commit_group;" ::: "memory")
#define CP_WAIT(n)  asm volatile("cp.async.wait_group %0;" :: "n"(n) : "memory")

__device__ __forceinline__ uint32_t smem_u32(const void* p) {
    uint32_t a;
    asm("{ .reg .u64 t; cvta.to.shared.u64 t, %1; cvt.u32.u64 %0, t; }" : "=r"(a) : "l"(p));
    return a;
}

// exp2 of two fp32 deltas -> packed half2 (lo = a, hi = b)
__device__ __forceinline__ uint32_t exp2_h2(float a, float b) {
    uint32_t h;
    asm("cvt.rn.f16x2.f32 %0, %1, %2;" : "=r"(h) : "f"(b), "f"(a));
    asm("ex2.approx.f16x2 %0, %0;" : "+r"(h));
    return h;
}

// XOR swizzle within a k16 tile: bit7 -> bit4
__device__ __forceinline__ uint32_t swz(uint32_t o) { return o ^ ((o & 0x80u) >> 3); }

// ============================================================
// scratch (device globals)
// ============================================================
__device__ float d_conv[3][B_][IC_][H_][W_];
__device__ __align__(16) __half d_qh[B_][L_][F_];   // 10*log2e*q, fp16
__device__ __align__(16) __half d_kh[B_][L_][F_];
__device__ __align__(16) __half d_vth[B_][FV_][L_]; // V transposed + ones row
__device__ float d_zi[B_][L_][F_];
__device__ __align__(16) float d_yvec[B_][C_][H_][W_];

// ============================================================
// Kernel 1: 1x1 convs at the mid depth slice only.
// ============================================================
__global__ void k_conv(const float* __restrict__ s, const float* __restrict__ g,
                       const float* __restrict__ gw, const float* __restrict__ gb,
                       const float* __restrict__ tw, const float* __restrict__ tb,
                       const float* __restrict__ pw, const float* __restrict__ pb) {
    __shared__ float wq[IC_ * C_], wv[IC_ * C_], wk[IC_ * C_];
    __shared__ float bq[IC_], bv[IC_], bk[IC_];
    const int tid = threadIdx.x;
    for (int i = tid; i < IC_ * C_; i += 128) { wq[i] = gw[i]; wv[i] = tw[i]; wk[i] = pw[i]; }
    if (tid < IC_) { bq[tid] = gb[tid]; bv[tid] = tb[tid]; bk[tid] = pb[tid]; }
    __syncthreads();

    const int y = blockIdx.x, b = blockIdx.y, x = tid;
    float aq[IC_], av[IC_], ak[IC_];
#pragma unroll
    for (int ic = 0; ic < IC_; ic++) { aq[ic] = bq[ic]; av[ic] = bv[ic]; ak[ic] = bk[ic]; }

    const size_t base = ((size_t)b * C_ * D_ + MID_) * (H_ * W_) + (size_t)y * W_ + x;
    const size_t cstride = (size_t)D_ * H_ * W_;
#pragma unroll 4
    for (int c = 0; c < C_; c++) {
        const float sv = s[base + c * cstride];
        const float gv = g[base + c * cstride];
#pragma unroll
        for (int ic = 0; ic < IC_; ic++) {
            aq[ic] += wq[ic * C_ + c] * sv;
            av[ic] += wv[ic * C_ + c] * gv;
            ak[ic] += wk[ic * C_ + c] * gv;
        }
    }
#pragma unroll
    for (int ic = 0; ic < IC_; ic++) {
        const int o = ((b * IC_ + ic) * H_ + y) * W_ + x;
        (&d_conv[0][0][0][0][0])[o] = aq[ic];
        (&d_conv[1][0][0][0][0])[o] = av[ic];
        (&d_conv[2][0][0][0][0])[o] = ak[ic];
    }
}

// ============================================================
// Kernel 2: patch extraction, locality-tiled. Also fills V ones rows.
// ============================================================
__global__ void k_patch() {
    __shared__ __half q_s[64][F_];
    __shared__ __half k_s[64][F_];
    const int hp = blockIdx.x, b = blockIdx.y;
    const int tid = threadIdx.x;

    for (int e = tid; e < 64 * 18; e += 128) {
        const int wp = e / 18, u = e - (e / 18) * 18;
        __half qv[8], kv[8];
#pragma unroll
        for (int j = 0; j < 8; j++) {
            const int f = u * 8 + j;
            const int c = f / 9, r = f - (f / 9) * 9;
            const int ki = r / 3, kj = r - (r / 3) * 3;
            const int y = hp * 2 - 1 + ki;
            const int x = wp * 2 - 1 + kj;
            const bool in = ((unsigned)y < (unsigned)H_) && ((unsigned)x < (unsigned)W_);
            const float q = in ? d_conv[0][b][c][y][x] : 0.0f;
            const float k = in ? d_conv[2][b][c][y][x] : 0.0f;
            qv[j] = __float2half_rn(q * (SCALE_ * LOG2E_));
            kv[j] = __float2half_rn(k);
        }
        *(uint4*)&q_s[wp][u * 8] = *(uint4*)qv;
        *(uint4*)&k_s[wp][u * 8] = *(uint4*)kv;
    }
    __syncthreads();
    for (int e = tid; e < 64 * 18; e += 128) {
        const int wp = e / 18, u = e - (e / 18) * 18;
        const int l = hp * 64 + wp;
        *(uint4*)&d_qh[b][l][u * 8] = *(const uint4*)&q_s[wp][u * 8];
        *(uint4*)&d_kh[b][l][u * 8] = *(const uint4*)&k_s[wp][u * 8];
    }
    __syncthreads();

    __half* v_s = &q_s[0][0];
    for (int e = tid; e < F_ * 8; e += 128) {
        const int f = e >> 3, u = e & 7;
        const int c = f / 9, r = f - (f / 9) * 9;
        const int ki = r / 3, kj = r - (r / 3) * 3;
        const int y = hp * 2 - 1 + ki;
        __half vv[8];
#pragma unroll
        for (int j = 0; j < 8; j++) {
            const int wp = u * 8 + j;
            const int x = wp * 2 - 1 + kj;
            const bool in = ((unsigned)y < (unsigned)H_) && ((unsigned)x < (unsigned)W_);
            vv[j] = __float2half_rn(in ? d_conv[1][b][c][y][x] : 0.0f);
        }
        *(uint4*)&v_s[f * 64 + u * 8] = *(uint4*)vv;
    }
    __syncthreads();
    for (int e = tid; e < F_ * 8; e += 128) {
        const int f = e >> 3, u = e & 7;
        *(uint4*)&d_vth[b][f][hp * 64 + u * 8] = *(const uint4*)&v_s[f * 64 + u * 8];
    }
    // ones padding rows: row 144 = 1.0, rows 145..151 = 0
    if (tid < 64) {
        const int fr = tid >> 3, u = tid & 7;
        const __half hv = (fr == 0) ? __float2half_rn(1.0f) : __float2half_rn(0.0f);
        __half vv[8];
#pragma unroll
        for (int j = 0; j < 8; j++) vv[j] = hv;
        *(uint4*)&d_vth[b][144 + fr][hp * 64 + u * 8] = *(uint4*)vv;
    }
}

// ============================================================
// Kernel 3: FUSED online-flash attention (R13 structure + ones-row l
// + f16x2 exp2). grid (32 row-tiles, B) = 128 CTAs, 512 threads.
// S-phase: 4x4 warps 32x32; PV-phase: 8x2 warps 16x72 (+ ones tile).
// ============================================================
__global__ __launch_bounds__(512, 1) void k_flash() {
    extern __shared__ char smc[];
    __shared__ float redmax[4][128];
    const uint32_t sbase = smem_u32(smc);
    float* alphas = (float*)(smc + ST_OFF);   // also reused as lfin at the end

    const int tid = threadIdx.x;
    const int lane = tid & 31;
    const int warp = tid >> 5;
    const int swr = warp >> 2, swc = warp & 3;   // S layout
    const int pwr = warp >> 1, pwc = warp & 1;   // PV layout
    const int g = lane >> 2;
    const int t = lane & 3;
    const int b = blockIdx.y;
    const int row0 = blockIdx.x * 128;

    float O[9][4];
#pragma unroll
    for (int n = 0; n < 9; n++)
#pragma unroll
        for (int j = 0; j < 4; j++) O[n][j] = 0.f;
    float ext[4] = {0.f, 0.f, 0.f, 0.f};   // ones-column accumulator (row sums)

    float mrow[4];
#pragma unroll
    for (int ri = 0; ri < 4; ri++) mrow[ri] = -1e30f;

    int rowIdx[4];
#pragma unroll
    for (int ri = 0; ri < 4; ri++)
        rowIdx[ri] = swr * 32 + (ri >> 1) * 16 + (ri & 1) * 8 + g;

    // prologue: Q (resident) + K chunk 0 + V chunk 0
    for (int e = tid; e < 128 * 18; e += 512) {
        const int r = e / 18, u = e - (e / 18) * 18;
        const int k16 = u >> 1, h = u & 1;
        const uint32_t o = (uint32_t)k16 * TILE_B + swz((uint32_t)(r * 32 + h * 16));
        const int fc = k16 * 16 + h * 8;
        cp_async16(sbase + Q_OFF + o, &d_qh[b][row0 + r][fc]);
        cp_async16(sbase + K_OFF + o, &d_kh[b][r][fc]);
    }
    for (int e = tid; e < FV_ * 16; e += 512) {
        const int f = e >> 4, u = e & 15;
        const int k16 = u >> 1, h = u & 1;
        const uint32_t o = (uint32_t)k16 * VTILE_B + swz((uint32_t)(f * 32 + h * 16));
        cp_async16(sbase + V_OFF + o, &d_vth[b][f][k16 * 16 + h * 8]);
    }
    CP_COMMIT();

    // LDSM lane offsets
    uint32_t aoffS[2], boffS[2];
#pragma unroll
    for (int m = 0; m < 2; m++)
        aoffS[m] = swz((uint32_t)((swr * 32 + m * 16 + (lane & 15)) * 32 + ((lane >> 4) & 1) * 16));
#pragma unroll
    for (int n16 = 0; n16 < 2; n16++)
        boffS[n16] = swz((uint32_t)((swc * 32 + n16 * 16 + (lane & 7) + ((lane >> 4) << 3)) * 32 +
                                    (((lane >> 3) & 1) << 4)));
    const uint32_t aoffP = swz((uint32_t)((pwr * 16 + (lane & 15)) * 32 + ((lane >> 4) & 1) * 16));
    uint32_t boffV[4];
#pragma unroll
    for (int p = 0; p < 4; p++)
        boffV[p] = swz((uint32_t)((pwc * 72 + p * 16 + (lane & 7) + ((lane >> 4) << 3)) * 32 +
                                  (((lane >> 3) & 1) << 4)));
    const uint32_t boffV2 = swz((uint32_t)((pwc * 72 + 64 + (lane & 7)) * 32 +
                                           (((lane >> 3) & 1) << 4)));
    const uint32_t boffOne = swz((uint32_t)((144 + (lane & 7)) * 32 +
                                            (((lane >> 3) & 1) << 4)));

    const uint32_t Qb = sbase + Q_OFF;
    const uint32_t Pb = sbase + P_OFF;

    for (int ct = 0; ct < 32; ct++) {
        const int buf = ct & 1;
        CP_WAIT(0);
        __syncthreads();   // (C) K/V[buf] ready; prior P consumed

        // issue next K/V chunk into other buffer
        if (ct < 31) {
            const int c1 = (ct + 1) * 128;
            const uint32_t kb1 = sbase + K_OFF + (uint32_t)(buf ^ 1) * QK_PLANE;
            const uint32_t vb1 = sbase + V_OFF + (uint32_t)(buf ^ 1) * V_PLANE;
            for (int e = tid; e < 128 * 18; e += 512) {
                const int r = e / 18, u = e - (e / 18) * 18;
                const int k16 = u >> 1, h = u & 1;
                const uint32_t o = (uint32_t)k16 * TILE_B + swz((uint32_t)(r * 32 + h * 16));
                cp_async16(kb1 + o, &d_kh[b][c1 + r][k16 * 16 + h * 8]);
            }
            for (int e = tid; e < FV_ * 16; e += 512) {
                const int f = e >> 4, u = e & 15;
                const int k16 = u >> 1, h = u & 1;
                const uint32_t o = (uint32_t)k16 * VTILE_B + swz((uint32_t)(f * 32 + h * 16));
                cp_async16(vb1 + o, &d_vth[b][f][c1 + k16 * 16 + h * 8]);
            }
            CP_COMMIT();
        }

        const uint32_t Kb = sbase + K_OFF + (uint32_t)buf * QK_PLANE;
        const uint32_t Vb = sbase + V_OFF + (uint32_t)buf * V_PLANE;

        // ---- S = Q' K^T (base-2 logits) ----
        float acc[2][4][4];
#pragma unroll
        for (int m = 0; m < 2; m++)
#pragma unroll
            for (int n = 0; n < 4; n++)
#pragma unroll
                for (int j = 0; j < 4; j++) acc[m][n][j] = 0.f;

#pragma unroll
        for (int k16 = 0; k16 < 9; k16++) {
            const uint32_t tb = (uint32_t)k16 * TILE_B;
            uint32_t a[2][4], bb[2][4];
            ldsm_x4(a[0], Qb + tb + aoffS[0]);
            ldsm_x4(a[1], Qb + tb + aoffS[1]);
            ldsm_x4(bb[0], Kb + tb + boffS[0]);
            ldsm_x4(bb[1], Kb + tb + boffS[1]);
#pragma unroll
            for (int m = 0; m < 2; m++) {
                mma16816(acc[m][0], a[m], bb[0][0], bb[0][1]);
                mma16816(acc[m][1], a[m], bb[0][2], bb[0][3]);
                mma16816(acc[m][2], a[m], bb[1][0], bb[1][1]);
                mma16816(acc[m][3], a[m], bb[1][2], bb[1][3]);
            }
        }

        // ---- warp-local row max into redmax ----
#pragma unroll
        for (int ri = 0; ri < 4; ri++) {
            const int m = ri >> 1, jb = (ri & 1) * 2;
            float mx = acc[m][0][jb];
#pragma unroll
            for (int n = 0; n < 4; n++)
                mx = fmaxf(mx, fmaxf(acc[m][n][jb], acc[m][n][jb + 1]));
            mx = fmaxf(mx, __shfl_xor_sync(0xffffffffu, mx, 1));
            mx = fmaxf(mx, __shfl_xor_sync(0xffffffffu, mx, 2));
            if (t == 0) redmax[swc][rowIdx[ri]] = mx;
        }
        __syncthreads();   // (A)

        // ---- P = exp2(S - m) via f16x2; alphas ----
#pragma unroll
        for (int ri = 0; ri < 4; ri++) {
            const int m = ri >> 1, jb = (ri & 1) * 2;
            const int row = rowIdx[ri];
            const float mnew = fmaxf(mrow[ri],
                fmaxf(fmaxf(redmax[0][row], redmax[1][row]),
                      fmaxf(redmax[2][row], redmax[3][row])));
            const float alpha = exp2f(mrow[ri] - mnew);
            mrow[ri] = mnew;
#pragma unroll
            for (int n = 0; n < 4; n++) {
                const uint32_t pv = exp2_h2(acc[m][n][jb] - mnew, acc[m][n][jb + 1] - mnew);
                const int col = swc * 32 + n * 8 + t * 2;
                const uint32_t off = (uint32_t)(col >> 4) * TILE_B +
                                     swz((uint32_t)(row * 32 + (col & 15) * 2));
                *(uint32_t*)(smc + P_OFF + off) = pv;
            }
            if (t == 0 && swc == 0) alphas[row] = alpha;
        }
        __syncthreads();   // (B) P + alphas ready

        // ---- O & ext rescale + O += P V (8 k16) ----
        {
            const float alA = alphas[pwr * 16 + g];
            const float alB = alphas[pwr * 16 + g + 8];
#pragma unroll
            for (int n = 0; n < 9; n++) {
                O[n][0] *= alA; O[n][1] *= alA;
                O[n][2] *= alB; O[n][3] *= alB;
            }
            ext[0] *= alA; ext[1] *= alA;
            ext[2] *= alB; ext[3] *= alB;
        }
#pragma unroll
        for (int k16 = 0; k16 < 8; k16++) {
            const uint32_t ptb = Pb + (uint32_t)k16 * TILE_B;
            const uint32_t vtb = Vb + (uint32_t)k16 * VTILE_B;
            uint32_t a[4];
            ldsm_x4(a, ptb + aoffP);
#pragma unroll
            for (int p = 0; p < 4; p++) {
                uint32_t bb[4];
                ldsm_x4(bb, vtb + boffV[p]);
                mma16816(O[2 * p],     a, bb[0], bb[1]);
                mma16816(O[2 * p + 1], a, bb[2], bb[3]);
            }
            {
                uint32_t bs[2];
                ldsm_x2(bs, vtb + boffV2);
                mma16816(O[8], a, bs[0], bs[1]);
            }
            if (pwc == 0) {
                uint32_t bo[2];
                ldsm_x2(bo, vtb + boffOne);
                mma16816(ext, a, bo[0], bo[1]);
            }
        }
    }

    // final: exchange row sums (ext col 144 lives in t==0, pwc==0), normalize
    __syncthreads();
    if (pwc == 0 && t == 0) {
        alphas[pwr * 16 + g]     = ext[0];   // row rA sum
        alphas[pwr * 16 + g + 8] = ext[2];   // row rB sum
    }
    __syncthreads();
    {
        const int rA = pwr * 16 + g;
        const int rB = rA + 8;
        const float liA = 1.0f / alphas[rA];
        const float liB = 1.0f / alphas[rB];
#pragma unroll
        for (int n = 0; n < 9; n++) {
            const int col = pwc * 72 + n * 8 + t * 2;
            *(float2*)&d_zi[b][row0 + rA][col] = make_float2(O[n][0] * liA, O[n][1] * liA);
            *(float2*)&d_zi[b][row0 + rB][col] = make_float2(O[n][2] * liB, O[n][3] * liB);
        }
    }
}

// ============================================================
// Kernel 4: fold (overlap-add + count normalize) + W_w conv -> yvec
// ============================================================
__global__ void k_fold(const float* __restrict__ Wmat, const float* __restrict__ Wb) {
    __shared__ float zs[IC_][W_];
    __shared__ float wsm[C_ * IC_];
    __shared__ float bsm[C_];
    const int x = threadIdx.x;
    const int y = blockIdx.x, b = blockIdx.y;
    for (int i = x; i < C_ * IC_; i += 128) wsm[i] = Wmat[i];
    if (x < C_) bsm[x] = Wb[x];

    float v[IC_];
#pragma unroll
    for (int ic = 0; ic < IC_; ic++) v[ic] = 0.f;
    int cnt = 0;
#pragma unroll
    for (int i = 0; i < 3; i++) {
        const int tY = y + 1 - i;
        if (tY < 0 || (tY & 1) || (tY >> 1) >= HP_) continue;
        const int hp = tY >> 1;
#pragma unroll
        for (int j = 0; j < 3; j++) {
            const int tX = x + 1 - j;
            if (tX < 0 || (tX & 1) || (tX >> 1) >= HP_) continue;
            const int wp = tX >> 1;
            const float* zrow = &d_zi[b][hp * 64 + wp][0];
            cnt++;
#pragma unroll
            for (int ic = 0; ic < IC_; ic++) v[ic] += zrow[ic * 9 + i * 3 + j];
        }
    }
    const float invc = 1.0f / (float)cnt;
#pragma unroll
    for (int ic = 0; ic < IC_; ic++) zs[ic][x] = v[ic] * invc;
    __syncthreads();

    for (int o = 0; o < C_; o++) {
        float a = bsm[o];
#pragma unroll
        for (int ic = 0; ic < IC_; ic++) a += wsm[o * IC_ + ic] * zs[ic][x];
        d_yvec[b][o][y][x] = a;
    }
}

// ============================================================
// Kernel 5: out = s + yvec (broadcast over D), float4 streaming.
// ============================================================
__global__ void k_out(const float4* __restrict__ s4, float4* __restrict__ out4) {
    const int idx = blockIdx.x * 256 + threadIdx.x;
    const int pix4 = idx & 4095;
    const int bo = (idx >> 12) >> 3;
    const float4 sv = s4[idx];
    const float4 yv = ((const float4*)&d_yvec[0][0][0][0])[bo * 4096 + pix4];
    out4[idx] = make_float4(sv.x + yv.x, sv.y + yv.y, sv.z + yv.z, sv.w + yv.w);
}

// ============================================================
extern "C" void kernel_launch(void* const* d_in, const int* /*in_sizes*/, int /*n_in*/,
                              void* d_out, int /*out_size*/) {
    const float* s   = (const float*)d_in[0];
    const float* g   = (const float*)d_in[1];
    const float* g_w = (const float*)d_in[2];
    const float* g_b = (const float*)d_in[3];
    const float* t_w = (const float*)d_in[4];
    const float* t_b = (const float*)d_in[5];
    const float* p_w = (const float*)d_in[6];
    const float* p_b = (const float*)d_in[7];
    const float* W_w = (const float*)d_in[8];
    const float* W_b = (const float*)d_in[9];
    float* out = (float*)d_out;

    cudaFuncSetAttribute(k_flash, cudaFuncAttributeMaxDynamicSharedMemorySize, FLASH_SMEM);

    k_conv<<<dim3(H_, B_), 128>>>(s, g, g_w, g_b, t_w, t_b, p_w, p_b);
    k_patch<<<dim3(HP_, B_), 128>>>();

    k_flash<<<dim3(32, B_), 512, FLASH_SMEM>>>();

    k_fold<<<dim3(H_, B_), 128>>>(W_w, W_b);

    const int total4 = (B_ * C_ * D_ * H_ * W_) / 4;
    k_out<<<total4 / 256, 256>>>((const float4*)s, (float4*)out);
}

// round 16
// speedup vs baseline: 1.4295x; 1.4295x over previous
#include <cuda_runtime.h>
#include <cuda_fp16.h>
#include <cstdint>

namespace {
constexpr int B_  = 4;
constexpr int C_  = 64;
constexpr int IC_ = 16;
constexpr int D_  = 8;
constexpr int H_  = 128;
constexpr int W_  = 128;
constexpr int MID_ = 4;
constexpr int HP_ = 64;
constexpr int L_  = 4096;
constexpr int F_  = 144;    // IC*3*3 = 9 * 16
constexpr float SCALE_ = 10.0f;
constexpr float LOG2E_ = 1.4426950408889634f;

// flash smem layout (bytes), k16-tiled swizzled operands
constexpr int TILE_B  = 4096;                 // 128 rows x 32B (Q/K/P)
constexpr int VTILE_B = 4608;                 // 144 rows x 32B (V)
constexpr int Q_OFF = 0;                      // 9*4096 = 36864
constexpr int K_OFF = 36864;                  // 2 bufs x 36864
constexpr int V_OFF = K_OFF + 2 * 36864;      // 110592; 2 bufs x 8*4608
constexpr int P_OFF = V_OFF + 2 * 36864;      // 184320; 8*4096 = 32768
constexpr int ST_OFF = P_OFF + 32768;         // 217088; alphas/lrun 2*512
constexpr int FLASH_SMEM = ST_OFF + 1024;     // 218112
}

// ============================================================
// helpers
// ============================================================
__device__ __forceinline__ void mma16816(float* c, const uint32_t* a,
                                         uint32_t b0, uint32_t b1) {
    asm volatile(
        "mma.sync.aligned.m16n8k16.row.col.f32.f16.f16.f32 "
        "{%0,%1,%2,%3}, {%4,%5,%6,%7}, {%8,%9}, {%0,%1,%2,%3};"
        : "+f"(c[0]), "+f"(c[1]), "+f"(c[2]), "+f"(c[3])
        : "r"(a[0]), "r"(a[1]), "r"(a[2]), "r"(a[3]), "r"(b0), "r"(b1));
}

__device__ __forceinline__ void ldsm_x4(uint32_t* r, uint32_t smaddr) {
    asm volatile("ldmatrix.sync.aligned.m8n8.x4.shared.b16 {%0,%1,%2,%3}, [%4];"
                 : "=r"(r[0]), "=r"(r[1]), "=r"(r[2]), "=r"(r[3]) : "r"(smaddr));
}
__device__ __forceinline__ void ldsm_x2(uint32_t* r, uint32_t smaddr) {
    asm volatile("ldmatrix.sync.aligned.m8n8.x2.shared.b16 {%0,%1}, [%2];"
                 : "=r"(r[0]), "=r"(r[1]) : "r"(smaddr));
}

__device__ __forceinline__ void cp_async16(uint32_t smaddr, const void* gptr) {
    asm volatile("cp.async.cg.shared.global [%0], [%1], 16;"
                 :: "r"(smaddr), "l"(gptr) : "memory");
}
#define CP_COMMIT() asm volatile("cp.async.commit_group;" ::: "memory")
#define CP_WAIT(n)  asm volatile("cp.async.wait_group %0;" :: "n"(n) : "memory")

__device__ __forceinline__ uint32_t smem_u32(const void* p) {
    uint32_t a;
    asm("{ .reg .u64 t; cvta.to.shared.u64 t, %1; cvt.u32.u64 %0, t; }" : "=r"(a) : "l"(p));
    return a;
}

// exp2 of two fp32 deltas -> packed half2 (lo = a, hi = b)
__device__ __forceinline__ uint32_t exp2_h2(float a, float b) {
    uint32_t h;
    asm("cvt.rn.f16x2.f32 %0, %1, %2;" : "=r"(h) : "f"(b), "f"(a));
    asm("ex2.approx.f16x2 %0, %0;" : "+r"(h));
    return h;
}

// XOR swizzle within a k16 tile: bit7 -> bit4
__device__ __forceinline__ uint32_t swz(uint32_t o) { return o ^ ((o & 0x80u) >> 3); }

// ============================================================
// scratch (device globals)
// ============================================================
__device__ float d_conv[3][B_][IC_][H_][W_];
__device__ __align__(16) __half d_qh[B_][L_][F_];   // 10*log2e*q, fp16
__device__ __align__(16) __half d_kh[B_][L_][F_];
__device__ __align__(16) __half d_vth[B_][F_][L_];  // V transposed
__device__ float d_zi[B_][L_][F_];
__device__ __align__(16) float d_yvec[B_][C_][H_][W_];

// ============================================================
// Kernel 1: 1x1 convs at the mid depth slice only.
// ============================================================
__global__ void k_conv(const float* __restrict__ s, const float* __restrict__ g,
                       const float* __restrict__ gw, const float* __restrict__ gb,
                       const float* __restrict__ tw, const float* __restrict__ tb,
                       const float* __restrict__ pw, const float* __restrict__ pb) {
    __shared__ float wq[IC_ * C_], wv[IC_ * C_], wk[IC_ * C_];
    __shared__ float bq[IC_], bv[IC_], bk[IC_];
    const int tid = threadIdx.x;
    for (int i = tid; i < IC_ * C_; i += 128) { wq[i] = gw[i]; wv[i] = tw[i]; wk[i] = pw[i]; }
    if (tid < IC_) { bq[tid] = gb[tid]; bv[tid] = tb[tid]; bk[tid] = pb[tid]; }
    __syncthreads();

    const int y = blockIdx.x, b = blockIdx.y, x = tid;
    float aq[IC_], av[IC_], ak[IC_];
#pragma unroll
    for (int ic = 0; ic < IC_; ic++) { aq[ic] = bq[ic]; av[ic] = bv[ic]; ak[ic] = bk[ic]; }

    const size_t base = ((size_t)b * C_ * D_ + MID_) * (H_ * W_) + (size_t)y * W_ + x;
    const size_t cstride = (size_t)D_ * H_ * W_;
#pragma unroll 4
    for (int c = 0; c < C_; c++) {
        const float sv = s[base + c * cstride];
        const float gv = g[base + c * cstride];
#pragma unroll
        for (int ic = 0; ic < IC_; ic++) {
            aq[ic] += wq[ic * C_ + c] * sv;
            av[ic] += wv[ic * C_ + c] * gv;
            ak[ic] += wk[ic * C_ + c] * gv;
        }
    }
#pragma unroll
    for (int ic = 0; ic < IC_; ic++) {
        const int o = ((b * IC_ + ic) * H_ + y) * W_ + x;
        (&d_conv[0][0][0][0][0])[o] = aq[ic];
        (&d_conv[1][0][0][0][0])[o] = av[ic];
        (&d_conv[2][0][0][0][0])[o] = ak[ic];
    }
}

// ============================================================
// Kernel 2: patch extraction, locality-tiled.
// ============================================================
__global__ void k_patch() {
    __shared__ __half q_s[64][F_];
    __shared__ __half k_s[64][F_];
    const int hp = blockIdx.x, b = blockIdx.y;
    const int tid = threadIdx.x;

    for (int e = tid; e < 64 * 18; e += 128) {
        const int wp = e / 18, u = e - (e / 18) * 18;
        __half qv[8], kv[8];
#pragma unroll
        for (int j = 0; j < 8; j++) {
            const int f = u * 8 + j;
            const int c = f / 9, r = f - (f / 9) * 9;
            const int ki = r / 3, kj = r - (r / 3) * 3;
            const int y = hp * 2 - 1 + ki;
            const int x = wp * 2 - 1 + kj;
            const bool in = ((unsigned)y < (unsigned)H_) && ((unsigned)x < (unsigned)W_);
            const float q = in ? d_conv[0][b][c][y][x] : 0.0f;
            const float k = in ? d_conv[2][b][c][y][x] : 0.0f;
            qv[j] = __float2half_rn(q * (SCALE_ * LOG2E_));
            kv[j] = __float2half_rn(k);
        }
        *(uint4*)&q_s[wp][u * 8] = *(uint4*)qv;
        *(uint4*)&k_s[wp][u * 8] = *(uint4*)kv;
    }
    __syncthreads();
    for (int e = tid; e < 64 * 18; e += 128) {
        const int wp = e / 18, u = e - (e / 18) * 18;
        const int l = hp * 64 + wp;
        *(uint4*)&d_qh[b][l][u * 8] = *(const uint4*)&q_s[wp][u * 8];
        *(uint4*)&d_kh[b][l][u * 8] = *(const uint4*)&k_s[wp][u * 8];
    }
    __syncthreads();

    __half* v_s = &q_s[0][0];
    for (int e = tid; e < F_ * 8; e += 128) {
        const int f = e >> 3, u = e & 7;
        const int c = f / 9, r = f - (f / 9) * 9;
        const int ki = r / 3, kj = r - (r / 3) * 3;
        const int y = hp * 2 - 1 + ki;
        __half vv[8];
#pragma unroll
        for (int j = 0; j < 8; j++) {
            const int wp = u * 8 + j;
            const int x = wp * 2 - 1 + kj;
            const bool in = ((unsigned)y < (unsigned)H_) && ((unsigned)x < (unsigned)W_);
            vv[j] = __float2half_rn(in ? d_conv[1][b][c][y][x] : 0.0f);
        }
        *(uint4*)&v_s[f * 64 + u * 8] = *(uint4*)vv;
    }
    __syncthreads();
    for (int e = tid; e < F_ * 8; e += 128) {
        const int f = e >> 3, u = e & 7;
        *(uint4*)&d_vth[b][f][hp * 64 + u * 8] = *(const uint4*)&v_s[f * 64 + u * 8];
    }
}

// ============================================================
// Kernel 3: FUSED online-flash attention (R13 structure; f16x2 exp2).
// grid (32 row-tiles, B) = 128 CTAs, 512 threads = 16 warps.
// ============================================================
__global__ __launch_bounds__(512, 1) void k_flash() {
    extern __shared__ char smc[];
    __shared__ float redmax[4][128];
    __shared__ float redsum[4][128];
    const uint32_t sbase = smem_u32(smc);
    float* alphas = (float*)(smc + ST_OFF);
    float* lrun   = alphas + 128;

    const int tid = threadIdx.x;
    const int lane = tid & 31;
    const int warp = tid >> 5;
    const int swr = warp >> 2, swc = warp & 3;   // S layout
    const int pwr = warp >> 1, pwc = warp & 1;   // PV layout
    const int g = lane >> 2;
    const int t = lane & 3;
    const int b = blockIdx.y;
    const int row0 = blockIdx.x * 128;

    if (tid < 128) lrun[tid] = 0.f;

    float O[9][4];
#pragma unroll
    for (int n = 0; n < 9; n++)
#pragma unroll
        for (int j = 0; j < 4; j++) O[n][j] = 0.f;

    float mrow[4];
#pragma unroll
    for (int ri = 0; ri < 4; ri++) mrow[ri] = -1e30f;

    int rowIdx[4];
#pragma unroll
    for (int ri = 0; ri < 4; ri++)
        rowIdx[ri] = swr * 32 + (ri >> 1) * 16 + (ri & 1) * 8 + g;

    // prologue: Q (resident) + K chunk 0 + V chunk 0
    for (int e = tid; e < 128 * 18; e += 512) {
        const int r = e / 18, u = e - (e / 18) * 18;
        const int k16 = u >> 1, h = u & 1;
        const uint32_t o = (uint32_t)k16 * TILE_B + swz((uint32_t)(r * 32 + h * 16));
        const int fc = k16 * 16 + h * 8;
        cp_async16(sbase + Q_OFF + o, &d_qh[b][row0 + r][fc]);
        cp_async16(sbase + K_OFF + o, &d_kh[b][r][fc]);
    }
    for (int e = tid; e < 144 * 16; e += 512) {
        const int f = e >> 4, u = e & 15;
        const int k16 = u >> 1, h = u & 1;
        const uint32_t o = (uint32_t)k16 * VTILE_B + swz((uint32_t)(f * 32 + h * 16));
        cp_async16(sbase + V_OFF + o, &d_vth[b][f][k16 * 16 + h * 8]);
    }
    CP_COMMIT();

    // LDSM lane offsets
    uint32_t aoffS[2], boffS[2];
#pragma unroll
    for (int m = 0; m < 2; m++)
        aoffS[m] = swz((uint32_t)((swr * 32 + m * 16 + (lane & 15)) * 32 + ((lane >> 4) & 1) * 16));
#pragma unroll
    for (int n16 = 0; n16 < 2; n16++)
        boffS[n16] = swz((uint32_t)((swc * 32 + n16 * 16 + (lane & 7) + ((lane >> 4) << 3)) * 32 +
                                    (((lane >> 3) & 1) << 4)));
    const uint32_t aoffP = swz((uint32_t)((pwr * 16 + (lane & 15)) * 32 + ((lane >> 4) & 1) * 16));
    uint32_t boffV[4];
#pragma unroll
    for (int p = 0; p < 4; p++)
        boffV[p] = swz((uint32_t)((pwc * 72 + p * 16 + (lane & 7) + ((lane >> 4) << 3)) * 32 +
                                  (((lane >> 3) & 1) << 4)));
    const uint32_t boffV2 = swz((uint32_t)((pwc * 72 + 64 + (lane & 7)) * 32 +
                                           (((lane >> 3) & 1) << 4)));

    const uint32_t Qb = sbase + Q_OFF;
    const uint32_t Pb = sbase + P_OFF;

    for (int ct = 0; ct < 32; ct++) {
        const int buf = ct & 1;
        CP_WAIT(0);
        __syncthreads();   // (C) K/V[buf] ready; prior P/red/lrun consumers done

        // issue next K/V chunk into other buffer
        if (ct < 31) {
            const int c1 = (ct + 1) * 128;
            const uint32_t kb1 = sbase + K_OFF + (uint32_t)(buf ^ 1) * 36864;
            const uint32_t vb1 = sbase + V_OFF + (uint32_t)(buf ^ 1) * 36864;
            for (int e = tid; e < 128 * 18; e += 512) {
                const int r = e / 18, u = e - (e / 18) * 18;
                const int k16 = u >> 1, h = u & 1;
                const uint32_t o = (uint32_t)k16 * TILE_B + swz((uint32_t)(r * 32 + h * 16));
                cp_async16(kb1 + o, &d_kh[b][c1 + r][k16 * 16 + h * 8]);
            }
            for (int e = tid; e < 144 * 16; e += 512) {
                const int f = e >> 4, u = e & 15;
                const int k16 = u >> 1, h = u & 1;
                const uint32_t o = (uint32_t)k16 * VTILE_B + swz((uint32_t)(f * 32 + h * 16));
                cp_async16(vb1 + o, &d_vth[b][f][c1 + k16 * 16 + h * 8]);
            }
            CP_COMMIT();
        }

        const uint32_t Kb = sbase + K_OFF + (uint32_t)buf * 36864;
        const uint32_t Vb = sbase + V_OFF + (uint32_t)buf * 36864;

        // ---- S = Q' K^T (base-2 logits) ----
        float acc[2][4][4];
#pragma unroll
        for (int m = 0; m < 2; m++)
#pragma unroll
            for (int n = 0; n < 4; n++)
#pragma unroll
                for (int j = 0; j < 4; j++) acc[m][n][j] = 0.f;

#pragma unroll
        for (int k16 = 0; k16 < 9; k16++) {
            const uint32_t tb = (uint32_t)k16 * TILE_B;
            uint32_t a[2][4], bb[2][4];
            ldsm_x4(a[0], Qb + tb + aoffS[0]);
            ldsm_x4(a[1], Qb + tb + aoffS[1]);
            ldsm_x4(bb[0], Kb + tb + boffS[0]);
            ldsm_x4(bb[1], Kb + tb + boffS[1]);
#pragma unroll
            for (int m = 0; m < 2; m++) {
                mma16816(acc[m][0], a[m], bb[0][0], bb[0][1]);
                mma16816(acc[m][1], a[m], bb[0][2], bb[0][3]);
                mma16816(acc[m][2], a[m], bb[1][0], bb[1][1]);
                mma16816(acc[m][3], a[m], bb[1][2], bb[1][3]);
            }
        }

        // ---- warp-local row max into redmax ----
#pragma unroll
        for (int ri = 0; ri < 4; ri++) {
            const int m = ri >> 1, jb = (ri & 1) * 2;
            float mx = acc[m][0][jb];
#pragma unroll
            for (int n = 0; n < 4; n++)
                mx = fmaxf(mx, fmaxf(acc[m][n][jb], acc[m][n][jb + 1]));
            mx = fmaxf(mx, __shfl_xor_sync(0xffffffffu, mx, 1));
            mx = fmaxf(mx, __shfl_xor_sync(0xffffffffu, mx, 2));
            if (t == 0) redmax[swc][rowIdx[ri]] = mx;
        }
        __syncthreads();   // (A)

        // ---- P = exp2(S - m) via f16x2; alphas; partial sums ----
#pragma unroll
        for (int ri = 0; ri < 4; ri++) {
            const int m = ri >> 1, jb = (ri & 1) * 2;
            const int row = rowIdx[ri];
            const float mnew = fmaxf(mrow[ri],
                fmaxf(fmaxf(redmax[0][row], redmax[1][row]),
                      fmaxf(redmax[2][row], redmax[3][row])));
            const float alpha = exp2f(mrow[ri] - mnew);
            mrow[ri] = mnew;
            float sum = 0.f;
#pragma unroll
            for (int n = 0; n < 4; n++) {
                const uint32_t pv = exp2_h2(acc[m][n][jb] - mnew, acc[m][n][jb + 1] - mnew);
                const float2 ef = __half22float2(*(const __half2*)&pv);
                sum += ef.x + ef.y;
                const int col = swc * 32 + n * 8 + t * 2;
                const uint32_t off = (uint32_t)(col >> 4) * TILE_B +
                                     swz((uint32_t)(row * 32 + (col & 15) * 2));
                *(uint32_t*)(smc + P_OFF + off) = pv;
            }
            sum += __shfl_xor_sync(0xffffffffu, sum, 1);
            sum += __shfl_xor_sync(0xffffffffu, sum, 2);
            if (t == 0) {
                redsum[swc][row] = sum;
                if (swc == 0) alphas[row] = alpha;
            }
        }
        __syncthreads();   // (B)

        if (tid < 128)
            lrun[tid] = lrun[tid] * alphas[tid] +
                        (redsum[0][tid] + redsum[1][tid]) +
                        (redsum[2][tid] + redsum[3][tid]);

        // ---- O rescale + O += P V (8 k16) ----
        {
            const float alA = alphas[pwr * 16 + g];
            const float alB = alphas[pwr * 16 + g + 8];
#pragma unroll
            for (int n = 0; n < 9; n++) {
                O[n][0] *= alA; O[n][1] *= alA;
                O[n][2] *= alB; O[n][3] *= alB;
            }
        }
#pragma unroll
        for (int k16 = 0; k16 < 8; k16++) {
            const uint32_t ptb = Pb + (uint32_t)k16 * TILE_B;
            const uint32_t vtb = Vb + (uint32_t)k16 * VTILE_B;
            uint32_t a[4];
            ldsm_x4(a, ptb + aoffP);
#pragma unroll
            for (int p = 0; p < 4; p++) {
                uint32_t bb[4];
                ldsm_x4(bb, vtb + boffV[p]);
                mma16816(O[2 * p],     a, bb[0], bb[1]);
                mma16816(O[2 * p + 1], a, bb[2], bb[3]);
            }
            {
                uint32_t bs[2];
                ldsm_x2(bs, vtb + boffV2);
                mma16816(O[8], a, bs[0], bs[1]);
            }
        }
    }

    __syncthreads();   // lrun final values visible to all
    {
        const int rA = pwr * 16 + g;
        const int rB = rA + 8;
        const float liA = 1.0f / lrun[rA];
        const float liB = 1.0f / lrun[rB];
#pragma unroll
        for (int n = 0; n < 9; n++) {
            const int col = pwc * 72 + n * 8 + t * 2;
            *(float2*)&d_zi[b][row0 + rA][col] = make_float2(O[n][0] * liA, O[n][1] * liA);
            *(float2*)&d_zi[b][row0 + rB][col] = make_float2(O[n][2] * liB, O[n][3] * liB);
        }
    }
}

// ============================================================
// Kernel 4: fold (overlap-add + count normalize) + W_w conv -> yvec
// ============================================================
__global__ void k_fold(const float* __restrict__ Wmat, const float* __restrict__ Wb) {
    __shared__ float zs[IC_][W_];
    __shared__ float wsm[C_ * IC_];
    __shared__ float bsm[C_];
    const int x = threadIdx.x;
    const int y = blockIdx.x, b = blockIdx.y;
    for (int i = x; i < C_ * IC_; i += 128) wsm[i] = Wmat[i];
    if (x < C_) bsm[x] = Wb[x];

    float v[IC_];
#pragma unroll
    for (int ic = 0; ic < IC_; ic++) v[ic] = 0.f;
    int cnt = 0;
#pragma unroll
    for (int i = 0; i < 3; i++) {
        const int tY = y + 1 - i;
        if (tY < 0 || (tY & 1) || (tY >> 1) >= HP_) continue;
        const int hp = tY >> 1;
#pragma unroll
        for (int j = 0; j < 3; j++) {
            const int tX = x + 1 - j;
            if (tX < 0 || (tX & 1) || (tX >> 1) >= HP_) continue;
            const int wp = tX >> 1;
            const float* zrow = &d_zi[b][hp * 64 + wp][0];
            cnt++;
#pragma unroll
            for (int ic = 0; ic < IC_; ic++) v[ic] += zrow[ic * 9 + i * 3 + j];
        }
    }
    const float invc = 1.0f / (float)cnt;
#pragma unroll
    for (int ic = 0; ic < IC_; ic++) zs[ic][x] = v[ic] * invc;
    __syncthreads();

    for (int o = 0; o < C_; o++) {
        float a = bsm[o];
#pragma unroll
        for (int ic = 0; ic < IC_; ic++) a += wsm[o * IC_ + ic] * zs[ic][x];
        d_yvec[b][o][y][x] = a;
    }
}

// ============================================================
// Kernel 5: out = s + yvec (broadcast over D), float4 streaming.
// ============================================================
__global__ void k_out(const float4* __restrict__ s4, float4* __restrict__ out4) {
    const int idx = blockIdx.x * 256 + threadIdx.x;
    const int pix4 = idx & 4095;
    const int bo = (idx >> 12) >> 3;
    const float4 sv = s4[idx];
    const float4 yv = ((const float4*)&d_yvec[0][0][0][0])[bo * 4096 + pix4];
    out4[idx] = make_float4(sv.x + yv.x, sv.y + yv.y, sv.z + yv.z, sv.w + yv.w);
}

// ============================================================
extern "C" void kernel_launch(void* const* d_in, const int* /*in_sizes*/, int /*n_in*/,
                              void* d_out, int /*out_size*/) {
    const float* s   = (const float*)d_in[0];
    const float* g   = (const float*)d_in[1];
    const float* g_w = (const float*)d_in[2];
    const float* g_b = (const float*)d_in[3];
    const float* t_w = (const float*)d_in[4];
    const float* t_b = (const float*)d_in[5];
    const float* p_w = (const float*)d_in[6];
    const float* p_b = (const float*)d_in[7];
    const float* W_w = (const float*)d_in[8];
    const float* W_b = (const float*)d_in[9];
    float* out = (float*)d_out;

    cudaFuncSetAttribute(k_flash, cudaFuncAttributeMaxDynamicSharedMemorySize, FLASH_SMEM);

    k_conv<<<dim3(H_, B_), 128>>>(s, g, g_w, g_b, t_w, t_b, p_w, p_b);
    k_patch<<<dim3(HP_, B_), 128>>>();

    k_flash<<<dim3(32, B_), 512, FLASH_SMEM>>>();

    k_fold<<<dim3(H_, B_), 128>>>(W_w, W_b);

    const int total4 = (B_ * C_ * D_ * H_ * W_) / 4;
    k_out<<<total4 / 256, 256>>>((const float4*)s, (float4*)out);
}

// round 17
// speedup vs baseline: 1.4655x; 1.0252x over previous
#include <cuda_runtime.h>
#include <cuda_fp16.h>
#include <cstdint>

namespace {
constexpr int B_  = 4;
constexpr int C_  = 64;
constexpr int IC_ = 16;
constexpr int D_  = 8;
constexpr int H_  = 128;
constexpr int W_  = 128;
constexpr int MID_ = 4;
constexpr int HP_ = 64;
constexpr int L_  = 4096;
constexpr int F_  = 144;    // IC*3*3 = 9 * 16
constexpr float SCALE_ = 10.0f;
constexpr float LOG2E_ = 1.4426950408889634f;

// flash smem layout (bytes), k16-tiled swizzled operands
constexpr int TILE_B  = 4096;                 // 128 rows x 32B (Q/K/P)
constexpr int VTILE_B = 4608;                 // 144 rows x 32B (V)
constexpr int Q_OFF = 0;                      // 9*4096 = 36864
constexpr int K_OFF = 36864;                  // 2 bufs x 36864
constexpr int V_OFF = K_OFF + 2 * 36864;      // 110592; 2 bufs x 8*4608
constexpr int P_OFF = V_OFF + 2 * 36864;      // 184320; 8*4096 = 32768
constexpr int ST_OFF = P_OFF + 32768;         // 217088; alphas/lrun 2*512
constexpr int FLASH_SMEM = ST_OFF + 1024;     // 218112
}

// ============================================================
// helpers
// ============================================================
__device__ __forceinline__ void mma16816(float* c, const uint32_t* a,
                                         uint32_t b0, uint32_t b1) {
    asm volatile(
        "mma.sync.aligned.m16n8k16.row.col.f32.f16.f16.f32 "
        "{%0,%1,%2,%3}, {%4,%5,%6,%7}, {%8,%9}, {%0,%1,%2,%3};"
        : "+f"(c[0]), "+f"(c[1]), "+f"(c[2]), "+f"(c[3])
        : "r"(a[0]), "r"(a[1]), "r"(a[2]), "r"(a[3]), "r"(b0), "r"(b1));
}

__device__ __forceinline__ void ldsm_x4(uint32_t* r, uint32_t smaddr) {
    asm volatile("ldmatrix.sync.aligned.m8n8.x4.shared.b16 {%0,%1,%2,%3}, [%4];"
                 : "=r"(r[0]), "=r"(r[1]), "=r"(r[2]), "=r"(r[3]) : "r"(smaddr));
}
__device__ __forceinline__ void ldsm_x2(uint32_t* r, uint32_t smaddr) {
    asm volatile("ldmatrix.sync.aligned.m8n8.x2.shared.b16 {%0,%1}, [%2];"
                 : "=r"(r[0]), "=r"(r[1]) : "r"(smaddr));
}

__device__ __forceinline__ void cp_async16(uint32_t smaddr, const void* gptr) {
    asm volatile("cp.async.cg.shared.global [%0], [%1], 16;"
                 :: "r"(smaddr), "l"(gptr) : "memory");
}
#define CP_COMMIT() asm volatile("cp.async.commit_group;" ::: "memory")
#define CP_WAIT(n)  asm volatile("cp.async.wait_group %0;" :: "n"(n) : "memory")

__device__ __forceinline__ uint32_t smem_u32(const void* p) {
    uint32_t a;
    asm("{ .reg .u64 t; cvta.to.shared.u64 t, %1; cvt.u32.u64 %0, t; }" : "=r"(a) : "l"(p));
    return a;
}

// exp2 of two fp32 deltas -> packed half2 (lo = a, hi = b)
__device__ __forceinline__ uint32_t exp2_h2(float a, float b) {
    uint32_t h;
    asm("cvt.rn.f16x2.f32 %0, %1, %2;" : "=r"(h) : "f"(b), "f"(a));
    asm("ex2.approx.f16x2 %0, %0;" : "+r"(h));
    return h;
}

// XOR swizzle within a k16 tile: bit7 -> bit4
__device__ __forceinline__ uint32_t swz(uint32_t o) { return o ^ ((o & 0x80u) >> 3); }

// ============================================================
// scratch (device globals)
// ============================================================
__device__ float d_conv[3][B_][IC_][H_][W_];
__device__ __align__(16) __half d_qh[B_][L_][F_];   // 10*log2e*q, fp16
__device__ __align__(16) __half d_kh[B_][L_][F_];
__device__ __align__(16) __half d_vth[B_][F_][L_];  // V transposed
__device__ float d_zit[B_][F_][L_];                 // zi transposed (f-major)
__device__ __align__(16) float d_yvec[B_][C_][H_][W_];

// ============================================================
// Kernel 1: 1x1 convs at the mid depth slice only.
// ============================================================
__global__ void k_conv(const float* __restrict__ s, const float* __restrict__ g,
                       const float* __restrict__ gw, const float* __restrict__ gb,
                       const float* __restrict__ tw, const float* __restrict__ tb,
                       const float* __restrict__ pw, const float* __restrict__ pb) {
    __shared__ float wq[IC_ * C_], wv[IC_ * C_], wk[IC_ * C_];
    __shared__ float bq[IC_], bv[IC_], bk[IC_];
    const int tid = threadIdx.x;
    for (int i = tid; i < IC_ * C_; i += 128) { wq[i] = gw[i]; wv[i] = tw[i]; wk[i] = pw[i]; }
    if (tid < IC_) { bq[tid] = gb[tid]; bv[tid] = tb[tid]; bk[tid] = pb[tid]; }
    __syncthreads();

    const int y = blockIdx.x, b = blockIdx.y, x = tid;
    float aq[IC_], av[IC_], ak[IC_];
#pragma unroll
    for (int ic = 0; ic < IC_; ic++) { aq[ic] = bq[ic]; av[ic] = bv[ic]; ak[ic] = bk[ic]; }

    const size_t base = ((size_t)b * C_ * D_ + MID_) * (H_ * W_) + (size_t)y * W_ + x;
    const size_t cstride = (size_t)D_ * H_ * W_;
#pragma unroll 8
    for (int c = 0; c < C_; c++) {
        const float sv = s[base + c * cstride];
        const float gv = g[base + c * cstride];
#pragma unroll
        for (int ic = 0; ic < IC_; ic++) {
            aq[ic] += wq[ic * C_ + c] * sv;
            av[ic] += wv[ic * C_ + c] * gv;
            ak[ic] += wk[ic * C_ + c] * gv;
        }
    }
#pragma unroll
    for (int ic = 0; ic < IC_; ic++) {
        const int o = ((b * IC_ + ic) * H_ + y) * W_ + x;
        (&d_conv[0][0][0][0][0])[o] = aq[ic];
        (&d_conv[1][0][0][0][0])[o] = av[ic];
        (&d_conv[2][0][0][0][0])[o] = ak[ic];
    }
}

// ============================================================
// Kernel 2: patch extraction, locality-tiled.
// ============================================================
__global__ void k_patch() {
    __shared__ __half q_s[64][F_];
    __shared__ __half k_s[64][F_];
    const int hp = blockIdx.x, b = blockIdx.y;
    const int tid = threadIdx.x;

    for (int e = tid; e < 64 * 18; e += 128) {
        const int wp = e / 18, u = e - (e / 18) * 18;
        __half qv[8], kv[8];
#pragma unroll
        for (int j = 0; j < 8; j++) {
            const int f = u * 8 + j;
            const int c = f / 9, r = f - (f / 9) * 9;
            const int ki = r / 3, kj = r - (r / 3) * 3;
            const int y = hp * 2 - 1 + ki;
            const int x = wp * 2 - 1 + kj;
            const bool in = ((unsigned)y < (unsigned)H_) && ((unsigned)x < (unsigned)W_);
            const float q = in ? d_conv[0][b][c][y][x] : 0.0f;
            const float k = in ? d_conv[2][b][c][y][x] : 0.0f;
            qv[j] = __float2half_rn(q * (SCALE_ * LOG2E_));
            kv[j] = __float2half_rn(k);
        }
        *(uint4*)&q_s[wp][u * 8] = *(uint4*)qv;
        *(uint4*)&k_s[wp][u * 8] = *(uint4*)kv;
    }
    __syncthreads();
    for (int e = tid; e < 64 * 18; e += 128) {
        const int wp = e / 18, u = e - (e / 18) * 18;
        const int l = hp * 64 + wp;
        *(uint4*)&d_qh[b][l][u * 8] = *(const uint4*)&q_s[wp][u * 8];
        *(uint4*)&d_kh[b][l][u * 8] = *(const uint4*)&k_s[wp][u * 8];
    }
    __syncthreads();

    __half* v_s = &q_s[0][0];
    for (int e = tid; e < F_ * 8; e += 128) {
        const int f = e >> 3, u = e & 7;
        const int c = f / 9, r = f - (f / 9) * 9;
        const int ki = r / 3, kj = r - (r / 3) * 3;
        const int y = hp * 2 - 1 + ki;
        __half vv[8];
#pragma unroll
        for (int j = 0; j < 8; j++) {
            const int wp = u * 8 + j;
            const int x = wp * 2 - 1 + kj;
            const bool in = ((unsigned)y < (unsigned)H_) && ((unsigned)x < (unsigned)W_);
            vv[j] = __float2half_rn(in ? d_conv[1][b][c][y][x] : 0.0f);
        }
        *(uint4*)&v_s[f * 64 + u * 8] = *(uint4*)vv;
    }
    __syncthreads();
    for (int e = tid; e < F_ * 8; e += 128) {
        const int f = e >> 3, u = e & 7;
        *(uint4*)&d_vth[b][f][hp * 64 + u * 8] = *(const uint4*)&v_s[f * 64 + u * 8];
    }
}

// ============================================================
// Kernel 3: FUSED online-flash attention (f16x2 exp2; transposed zi out).
// grid (32 row-tiles, B) = 128 CTAs, 512 threads = 16 warps.
// ============================================================
__global__ __launch_bounds__(512, 1) void k_flash() {
    extern __shared__ char smc[];
    __shared__ float redmax[4][128];
    __shared__ float redsum[4][128];
    const uint32_t sbase = smem_u32(smc);
    float* alphas = (float*)(smc + ST_OFF);
    float* lrun   = alphas + 128;

    const int tid = threadIdx.x;
    const int lane = tid & 31;
    const int warp = tid >> 5;
    const int swr = warp >> 2, swc = warp & 3;   // S layout
    const int pwr = warp >> 1, pwc = warp & 1;   // PV layout
    const int g = lane >> 2;
    const int t = lane & 3;
    const int b = blockIdx.y;
    const int row0 = blockIdx.x * 128;

    if (tid < 128) lrun[tid] = 0.f;

    float O[9][4];
#pragma unroll
    for (int n = 0; n < 9; n++)
#pragma unroll
        for (int j = 0; j < 4; j++) O[n][j] = 0.f;

    float mrow[4];
#pragma unroll
    for (int ri = 0; ri < 4; ri++) mrow[ri] = -1e30f;

    int rowIdx[4];
#pragma unroll
    for (int ri = 0; ri < 4; ri++)
        rowIdx[ri] = swr * 32 + (ri >> 1) * 16 + (ri & 1) * 8 + g;

    // prologue: Q (resident) + K chunk 0 + V chunk 0
    for (int e = tid; e < 128 * 18; e += 512) {
        const int r = e / 18, u = e - (e / 18) * 18;
        const int k16 = u >> 1, h = u & 1;
        const uint32_t o = (uint32_t)k16 * TILE_B + swz((uint32_t)(r * 32 + h * 16));
        const int fc = k16 * 16 + h * 8;
        cp_async16(sbase + Q_OFF + o, &d_qh[b][row0 + r][fc]);
        cp_async16(sbase + K_OFF + o, &d_kh[b][r][fc]);
    }
    for (int e = tid; e < 144 * 16; e += 512) {
        const int f = e >> 4, u = e & 15;
        const int k16 = u >> 1, h = u & 1;
        const uint32_t o = (uint32_t)k16 * VTILE_B + swz((uint32_t)(f * 32 + h * 16));
        cp_async16(sbase + V_OFF + o, &d_vth[b][f][k16 * 16 + h * 8]);
    }
    CP_COMMIT();

    // LDSM lane offsets
    uint32_t aoffS[2], boffS[2];
#pragma unroll
    for (int m = 0; m < 2; m++)
        aoffS[m] = swz((uint32_t)((swr * 32 + m * 16 + (lane & 15)) * 32 + ((lane >> 4) & 1) * 16));
#pragma unroll
    for (int n16 = 0; n16 < 2; n16++)
        boffS[n16] = swz((uint32_t)((swc * 32 + n16 * 16 + (lane & 7) + ((lane >> 4) << 3)) * 32 +
                                    (((lane >> 3) & 1) << 4)));
    const uint32_t aoffP = swz((uint32_t)((pwr * 16 + (lane & 15)) * 32 + ((lane >> 4) & 1) * 16));
    uint32_t boffV[4];
#pragma unroll
    for (int p = 0; p < 4; p++)
        boffV[p] = swz((uint32_t)((pwc * 72 + p * 16 + (lane & 7) + ((lane >> 4) << 3)) * 32 +
                                  (((lane >> 3) & 1) << 4)));
    const uint32_t boffV2 = swz((uint32_t)((pwc * 72 + 64 + (lane & 7)) * 32 +
                                           (((lane >> 3) & 1) << 4)));

    const uint32_t Qb = sbase + Q_OFF;
    const uint32_t Pb = sbase + P_OFF;

    for (int ct = 0; ct < 32; ct++) {
        const int buf = ct & 1;
        CP_WAIT(0);
        __syncthreads();   // (C) K/V[buf] ready; prior P/red/lrun consumers done

        // issue next K/V chunk into other buffer
        if (ct < 31) {
            const int c1 = (ct + 1) * 128;
            const uint32_t kb1 = sbase + K_OFF + (uint32_t)(buf ^ 1) * 36864;
            const uint32_t vb1 = sbase + V_OFF + (uint32_t)(buf ^ 1) * 36864;
            for (int e = tid; e < 128 * 18; e += 512) {
                const int r = e / 18, u = e - (e / 18) * 18;
                const int k16 = u >> 1, h = u & 1;
                const uint32_t o = (uint32_t)k16 * TILE_B + swz((uint32_t)(r * 32 + h * 16));
                cp_async16(kb1 + o, &d_kh[b][c1 + r][k16 * 16 + h * 8]);
            }
            for (int e = tid; e < 144 * 16; e += 512) {
                const int f = e >> 4, u = e & 15;
                const int k16 = u >> 1, h = u & 1;
                const uint32_t o = (uint32_t)k16 * VTILE_B + swz((uint32_t)(f * 32 + h * 16));
                cp_async16(vb1 + o, &d_vth[b][f][c1 + k16 * 16 + h * 8]);
            }
            CP_COMMIT();
        }

        const uint32_t Kb = sbase + K_OFF + (uint32_t)buf * 36864;
        const uint32_t Vb = sbase + V_OFF + (uint32_t)buf * 36864;

        // ---- S = Q' K^T (base-2 logits) ----
        float acc[2][4][4];
#pragma unroll
        for (int m = 0; m < 2; m++)
#pragma unroll
            for (int n = 0; n < 4; n++)
#pragma unroll
                for (int j = 0; j < 4; j++) acc[m][n][j] = 0.f;

#pragma unroll
        for (int k16 = 0; k16 < 9; k16++) {
            const uint32_t tb = (uint32_t)k16 * TILE_B;
            uint32_t a[2][4], bb[2][4];
            ldsm_x4(a[0], Qb + tb + aoffS[0]);
            ldsm_x4(a[1], Qb + tb + aoffS[1]);
            ldsm_x4(bb[0], Kb + tb + boffS[0]);
            ldsm_x4(bb[1], Kb + tb + boffS[1]);
#pragma unroll
            for (int m = 0; m < 2; m++) {
                mma16816(acc[m][0], a[m], bb[0][0], bb[0][1]);
                mma16816(acc[m][1], a[m], bb[0][2], bb[0][3]);
                mma16816(acc[m][2], a[m], bb[1][0], bb[1][1]);
                mma16816(acc[m][3], a[m], bb[1][2], bb[1][3]);
            }
        }

        // ---- warp-local row max into redmax ----
#pragma unroll
        for (int ri = 0; ri < 4; ri++) {
            const int m = ri >> 1, jb = (ri & 1) * 2;
            float mx = acc[m][0][jb];
#pragma unroll
            for (int n = 0; n < 4; n++)
                mx = fmaxf(mx, fmaxf(acc[m][n][jb], acc[m][n][jb + 1]));
            mx = fmaxf(mx, __shfl_xor_sync(0xffffffffu, mx, 1));
            mx = fmaxf(mx, __shfl_xor_sync(0xffffffffu, mx, 2));
            if (t == 0) redmax[swc][rowIdx[ri]] = mx;
        }
        __syncthreads();   // (A)

        // ---- P = exp2(S - m) via f16x2; alphas; partial sums ----
#pragma unroll
        for (int ri = 0; ri < 4; ri++) {
            const int m = ri >> 1, jb = (ri & 1) * 2;
            const int row = rowIdx[ri];
            const float mnew = fmaxf(mrow[ri],
                fmaxf(fmaxf(redmax[0][row], redmax[1][row]),
                      fmaxf(redmax[2][row], redmax[3][row])));
            const float alpha = exp2f(mrow[ri] - mnew);
            mrow[ri] = mnew;
            float sum = 0.f;
#pragma unroll
            for (int n = 0; n < 4; n++) {
                const uint32_t pv = exp2_h2(acc[m][n][jb] - mnew, acc[m][n][jb + 1] - mnew);
                const float2 ef = __half22float2(*(const __half2*)&pv);
                sum += ef.x + ef.y;
                const int col = swc * 32 + n * 8 + t * 2;
                const uint32_t off = (uint32_t)(col >> 4) * TILE_B +
                                     swz((uint32_t)(row * 32 + (col & 15) * 2));
                *(uint32_t*)(smc + P_OFF + off) = pv;
            }
            sum += __shfl_xor_sync(0xffffffffu, sum, 1);
            sum += __shfl_xor_sync(0xffffffffu, sum, 2);
            if (t == 0) {
                redsum[swc][row] = sum;
                if (swc == 0) alphas[row] = alpha;
            }
        }
        __syncthreads();   // (B)

        if (tid < 128)
            lrun[tid] = lrun[tid] * alphas[tid] +
                        (redsum[0][tid] + redsum[1][tid]) +
                        (redsum[2][tid] + redsum[3][tid]);

        // ---- O rescale + O += P V (8 k16) ----
        {
            const float alA = alphas[pwr * 16 + g];
            const float alB = alphas[pwr * 16 + g + 8];
#pragma unroll
            for (int n = 0; n < 9; n++) {
                O[n][0] *= alA; O[n][1] *= alA;
                O[n][2] *= alB; O[n][3] *= alB;
            }
        }
#pragma unroll
        for (int k16 = 0; k16 < 8; k16++) {
            const uint32_t ptb = Pb + (uint32_t)k16 * TILE_B;
            const uint32_t vtb = Vb + (uint32_t)k16 * VTILE_B;
            uint32_t a[4];
            ldsm_x4(a, ptb + aoffP);
#pragma unroll
            for (int p = 0; p < 4; p++) {
                uint32_t bb[4];
                ldsm_x4(bb, vtb + boffV[p]);
                mma16816(O[2 * p],     a, bb[0], bb[1]);
                mma16816(O[2 * p + 1], a, bb[2], bb[3]);
            }
            {
                uint32_t bs[2];
                ldsm_x2(bs, vtb + boffV2);
                mma16816(O[8], a, bs[0], bs[1]);
            }
        }
    }

    __syncthreads();   // lrun final values visible to all
    {
        const int rA = pwr * 16 + g;
        const int rB = rA + 8;
        const float liA = 1.0f / lrun[rA];
        const float liB = 1.0f / lrun[rB];
#pragma unroll
        for (int n = 0; n < 9; n++) {
            const int col = pwc * 72 + n * 8 + t * 2;
            d_zit[b][col][row0 + rA]     = O[n][0] * liA;
            d_zit[b][col + 1][row0 + rA] = O[n][1] * liA;
            d_zit[b][col][row0 + rB]     = O[n][2] * liB;
            d_zit[b][col + 1][row0 + rB] = O[n][3] * liB;
        }
    }
}

// ============================================================
// Kernel 4: fold (overlap-add + count normalize) + W_w conv -> yvec.
// Reads transposed zi coalesced.
// ============================================================
__global__ void k_fold(const float* __restrict__ Wmat, const float* __restrict__ Wb) {
    __shared__ float zs[IC_][W_];
    __shared__ float wsm[C_ * IC_];
    __shared__ float bsm[C_];
    const int x = threadIdx.x;
    const int y = blockIdx.x, b = blockIdx.y;
    for (int i = x; i < C_ * IC_; i += 128) wsm[i] = Wmat[i];
    if (x < C_) bsm[x] = Wb[x];

    bool vij[3][3];
    int hpv[3], wpv[3];
    int cnt = 0;
#pragma unroll
    for (int i = 0; i < 3; i++) {
        const int tY = y + 1 - i;
        const bool vy = (tY >= 0) && !(tY & 1) && ((tY >> 1) < HP_);
        hpv[i] = tY >> 1;
#pragma unroll
        for (int j = 0; j < 3; j++) {
            const int tX = x + 1 - j;
            const bool vx = (tX >= 0) && !(tX & 1) && ((tX >> 1) < HP_);
            if (i == 0) wpv[j] = tX >> 1;
            vij[i][j] = vy && vx;
            if (vij[i][j]) cnt++;
        }
    }

    float v[IC_];
#pragma unroll
    for (int ic = 0; ic < IC_; ic++) v[ic] = 0.f;
#pragma unroll
    for (int ic = 0; ic < IC_; ic++) {
#pragma unroll
        for (int i = 0; i < 3; i++) {
#pragma unroll
            for (int j = 0; j < 3; j++) {
                if (vij[i][j])
                    v[ic] += d_zit[b][ic * 9 + i * 3 + j][hpv[i] * 64 + wpv[j]];
            }
        }
    }
    const float invc = 1.0f / (float)cnt;
#pragma unroll
    for (int ic = 0; ic < IC_; ic++) zs[ic][x] = v[ic] * invc;
    __syncthreads();

    for (int o = 0; o < C_; o++) {
        float a = bsm[o];
#pragma unroll
        for (int ic = 0; ic < IC_; ic++) a += wsm[o * IC_ + ic] * zs[ic][x];
        d_yvec[b][o][y][x] = a;
    }
}

// ============================================================
// Kernel 5: out = s + yvec (broadcast over D), float4 streaming.
// ============================================================
__global__ void k_out(const float4* __restrict__ s4, float4* __restrict__ out4) {
    const int idx = blockIdx.x * 256 + threadIdx.x;
    const int pix4 = idx & 4095;
    const int bo = (idx >> 12) >> 3;
    const float4 sv = s4[idx];
    const float4 yv = ((const float4*)&d_yvec[0][0][0][0])[bo * 4096 + pix4];
    out4[idx] = make_float4(sv.x + yv.x, sv.y + yv.y, sv.z + yv.z, sv.w + yv.w);
}

// ============================================================
extern "C" void kernel_launch(void* const* d_in, const int* /*in_sizes*/, int /*n_in*/,
                              void* d_out, int /*out_size*/) {
    const float* s   = (const float*)d_in[0];
    const float* g   = (const float*)d_in[1];
    const float* g_w = (const float*)d_in[2];
    const float* g_b = (const float*)d_in[3];
    const float* t_w = (const float*)d_in[4];
    const float* t_b = (const float*)d_in[5];
    const float* p_w = (const float*)d_in[6];
    const float* p_b = (const float*)d_in[7];
    const float* W_w = (const float*)d_in[8];
    const float* W_b = (const float*)d_in[9];
    float* out = (float*)d_out;

    cudaFuncSetAttribute(k_flash, cudaFuncAttributeMaxDynamicSharedMemorySize, FLASH_SMEM);

    k_conv<<<dim3(H_, B_), 128>>>(s, g, g_w, g_b, t_w, t_b, p_w, p_b);
    k_patch<<<dim3(HP_, B_), 128>>>();

    k_flash<<<dim3(32, B_), 512, FLASH_SMEM>>>();

    k_fold<<<dim3(H_, B_), 128>>>(W_w, W_b);

    const int total4 = (B_ * C_ * D_ * H_ * W_) / 4;
    k_out<<<total4 / 256, 256>>>((const float4*)s, (float4*)out);
}